// round 15
// baseline (speedup 1.0000x reference)
#include <cuda_runtime.h>
#include <cuda_fp16.h>
#include <cstdint>
#include <cstddef>

// ---------------- problem dimensions ----------------
static constexpr int N_NODES = 16384;
static constexpr int NE      = 131072;
static constexpr int NE_RO   = 32768;
static constexpr int D       = 1024;
static constexpr int DL      = 300;
static constexpr int DS      = 16;
static constexpr int NC      = 117;

// ---------------- fp32 scratch (readout precursors) ----------------
static constexpr size_t SZ_NC   = (size_t)N_NODES * NC;
static constexpr size_t SZ_SPRO = (size_t)NE_RO * NC;
static constexpr size_t OFF_RD   = 0;
static constexpr size_t OFF_RS   = OFF_RD + SZ_NC;
static constexpr size_t OFF_SPRO = OFF_RS + SZ_NC;
static constexpr size_t TOTAL_F32 = OFF_SPRO + SZ_SPRO;
__device__ float g_scratch[TOTAL_F32];

// ---------------- fp16 scratch ----------------
static constexpr size_t HOFF_FA   = 0;                               // [N][2048] = [feat|AGG]
static constexpr size_t HSZ_FA    = (size_t)N_NODES * 2048;
static constexpr size_t HOFF_WA   = HOFF_FA + HSZ_FA;                // [N][608]  = [w2v|AGGL|pad]
static constexpr size_t HSZ_WA    = (size_t)N_NODES * 608;
static constexpr size_t HOFF_NFA  = HOFF_WA + HSZ_WA;                // [N][1328] = [NF|NFL|pad]
static constexpr size_t HSZ_NFA   = (size_t)N_NODES * 1328;
static constexpr size_t HOFF_P1   = HOFF_NFA + HSZ_NFA;
static constexpr size_t HSZ_P     = (size_t)N_NODES * 1024;
static constexpr size_t HOFF_P2   = HOFF_P1 + HSZ_P;
static constexpr size_t HOFF_Q1   = HOFF_P2 + HSZ_P;
static constexpr size_t HSZ_Q     = (size_t)N_NODES * 304;
static constexpr size_t HOFF_Q2   = HOFF_Q1 + HSZ_Q;
static constexpr size_t HOFF_SP   = HOFF_Q2 + HSZ_Q;
static constexpr size_t HSZ_SP    = (size_t)NE * 1024;
static constexpr size_t HOFF_SFH  = HOFF_SP + HSZ_SP;
static constexpr size_t HSZ_SFH   = (size_t)NE * 16;
static constexpr size_t HOFF_SFRO = HOFF_SFH + HSZ_SFH;
static constexpr size_t HSZ_SFRO  = (size_t)NE_RO * 16;
static constexpr size_t TOTAL_H   = HOFF_SFRO + HSZ_SFRO;
__device__ __half g_hscratch[TOTAL_H];

// ---------------- packed fp16x2 weights (k-pairs, row stride = Nn u32) ----------------
static constexpr size_t POFF_WE1  = 0;                    // 512x1024
static constexpr size_t POFF_WE2  = POFF_WE1 + 512 * 1024;
static constexpr size_t POFF_WS   = POFF_WE2 + 512 * 1024;   // 8x1024
static constexpr size_t POFF_WEL1 = POFF_WS + 8 * 1024;      // 150x300
static constexpr size_t POFF_WEL2 = POFF_WEL1 + 150 * 300;
static constexpr size_t POFF_WNU  = POFF_WEL2 + 150 * 300;   // 1024x1024
static constexpr size_t POFF_WNUL = POFF_WNU + 1024 * 1024;  // 300x300
static constexpr size_t POFF_WRD  = POFF_WNUL + 300 * 300;   // 662x117 (pad to mult of 4)
static constexpr size_t POFF_WRS  = POFF_WRD + 77456;
static constexpr size_t POFF_WSP  = POFF_WRS + 77456;        // 8x117
static constexpr size_t TOTAL_P   = POFF_WSP + 8 * 117 + 16;
__device__ uint32_t g_pscratch[TOTAL_P];

// int scratch
static constexpr size_t IOFF_DEG  = 0;
static constexpr size_t IOFF_RS_  = IOFF_DEG + N_NODES;
static constexpr size_t IOFF_CUR  = IOFF_RS_ + N_NODES + 1;
static constexpr size_t IOFF_PERM = IOFF_CUR + N_NODES;
__device__ int g_iscratch[IOFF_PERM + NE];

// ---------------- CSR build kernels ----------------
__global__ void zero_int_kernel(int* __restrict__ p, int n) {
    int i = blockIdx.x * blockDim.x + threadIdx.x;
    if (i < n) p[i] = 0;
}
__global__ void hist_kernel(const int* __restrict__ edst, int* __restrict__ deg) {
    int e = blockIdx.x * blockDim.x + threadIdx.x;
    if (e < NE) atomicAdd(&deg[edst[e]], 1);
}
__global__ __launch_bounds__(512)
void scan_kernel(const int* __restrict__ deg, int* __restrict__ row_start,
                 int* __restrict__ cursor) {
    __shared__ int part[512];
    int tid = threadIdx.x;
    int base = tid * 32;
    int loc[32];
    int s = 0;
#pragma unroll
    for (int j = 0; j < 32; j++) { loc[j] = s; s += deg[base + j]; }
    part[tid] = s;
    __syncthreads();
    for (int off = 1; off < 512; off <<= 1) {
        int v = (tid >= off) ? part[tid - off] : 0;
        __syncthreads();
        part[tid] += v;
        __syncthreads();
    }
    int pre = (tid > 0) ? part[tid - 1] : 0;
#pragma unroll
    for (int j = 0; j < 32; j++) {
        int v = pre + loc[j];
        row_start[base + j] = v;
        cursor[base + j] = v;
    }
    if (tid == 511) row_start[N_NODES] = part[511];
}
__global__ void scatter_kernel(const int* __restrict__ edst, int* __restrict__ cursor,
                               int* __restrict__ perm) {
    int e = blockIdx.x * blockDim.x + threadIdx.x;
    if (e < NE) {
        int pos = atomicAdd(&cursor[edst[e]], 1);
        perm[pos] = e;
    }
}

// ---------------- fp16 helpers ----------------
__device__ __forceinline__ uint32_t f16_pack(float f0, float f1) {
    __half2 h = __floats2half2_rn(f0, f1);
    return *(uint32_t*)&h;
}
__device__ __forceinline__ void mma_f16(float* c, const uint32_t* a, const uint32_t* b) {
    asm volatile("mma.sync.aligned.m16n8k16.row.col.f32.f16.f16.f32 "
        "{%0,%1,%2,%3}, {%4,%5,%6,%7}, {%8,%9}, {%0,%1,%2,%3};"
        : "+f"(c[0]), "+f"(c[1]), "+f"(c[2]), "+f"(c[3])
        : "r"(a[0]), "r"(a[1]), "r"(a[2]), "r"(a[3]), "r"(b[0]), "r"(b[1]));
}
__device__ __forceinline__ uint32_t smem_u32(const void* p) {
    uint32_t a;
    asm("{ .reg .u64 t; cvta.to.shared.u64 t, %1; cvt.u32.u64 %0, t; }" : "=r"(a) : "l"(p));
    return a;
}
__device__ __forceinline__ void cp_async16(uint32_t dst, const void* src, int src_bytes) {
    asm volatile("cp.async.cg.shared.global [%0], [%1], 16, %2;"
                 :: "r"(dst), "l"(src), "r"(src_bytes) : "memory");
}
__device__ __forceinline__ void cp_async4(uint32_t dst, const void* src, int src_bytes) {
    asm volatile("cp.async.ca.shared.global [%0], [%1], 4, %2;"
                 :: "r"(dst), "l"(src), "r"(src_bytes) : "memory");
}
#define CP_COMMIT() asm volatile("cp.async.commit_group;" ::: "memory")
#define CP_WAIT(N)  asm volatile("cp.async.wait_group %0;" :: "n"(N) : "memory")

// ---------------- conversion kernels ----------------
__global__ __launch_bounds__(256)
void conv_node_kernel(const float* __restrict__ feat, const float* __restrict__ w2v,
                      __half* __restrict__ FA, __half* __restrict__ WA,
                      __half* __restrict__ NFA)
{
    int n = blockIdx.x, tid = threadIdx.x;
    float4 f = *(const float4*)(feat + (size_t)n * 1024 + tid * 4);
    __half2 h0 = __floats2half2_rn(f.x, f.y);
    __half2 h1 = __floats2half2_rn(f.z, f.w);
    uint2 u; u.x = *(uint32_t*)&h0; u.y = *(uint32_t*)&h1;
    *(uint2*)(FA + (size_t)n * 2048 + tid * 4) = u;
    if (tid < 75) {
        float4 w = *(const float4*)(w2v + (size_t)n * 300 + tid * 4);
        __half2 g0 = __floats2half2_rn(w.x, w.y);
        __half2 g1 = __floats2half2_rn(w.z, w.w);
        uint2 v; v.x = *(uint32_t*)&g0; v.y = *(uint32_t*)&g1;
        *(uint2*)(WA + (size_t)n * 608 + tid * 4) = v;
    } else if (tid == 75) {
        uint2 z = make_uint2(0, 0);
        *(uint2*)(WA + (size_t)n * 608 + 600) = z;
        *(uint2*)(WA + (size_t)n * 608 + 604) = z;
    } else if (tid == 76) {
        uint2 z = make_uint2(0, 0);
        *(uint2*)(NFA + (size_t)n * 1328 + 1324) = z;
    }
}

__global__ void conv_sf_kernel(const float* __restrict__ s_f, const float* __restrict__ s_f_ro,
                               __half* __restrict__ sfh, __half* __restrict__ sfroh)
{
    size_t i = (size_t)blockIdx.x * blockDim.x + threadIdx.x;
    size_t n1 = (size_t)NE * 8;
    size_t tot = n1 + (size_t)NE_RO * 8;
    if (i >= tot) return;
    if (i < n1) {
        float2 f = *(const float2*)(s_f + i * 2);
        __half2 h = __floats2half2_rn(f.x, f.y);
        *(uint32_t*)(sfh + i * 2) = *(uint32_t*)&h;
    } else {
        size_t j = i - n1;
        float2 f = *(const float2*)(s_f_ro + j * 2);
        __half2 h = __floats2half2_rn(f.x, f.y);
        *(uint32_t*)(sfroh + j * 2) = *(uint32_t*)&h;
    }
}

// ---------------- weight k-pair packing: dst[kp][n] = half2(src[2kp][n], src[2kp+1][n]) ----------------
struct PJob { const float* src; int ldsrc; int K; int Nn; uint32_t* dst; };
struct PJobs { PJob j[11]; };

__global__ __launch_bounds__(256)
void wpack_kernel(PJobs J)
{
    PJob jb = J.j[blockIdx.z];
    int kp = blockIdx.y;
    int n  = blockIdx.x * 256 + threadIdx.x;
    if (2 * kp >= jb.K || n >= jb.Nn) return;
    float f0 = jb.src[(size_t)(2 * kp) * jb.ldsrc + n];
    float f1 = (2 * kp + 1 < jb.K) ? jb.src[(size_t)(2 * kp + 1) * jb.ldsrc + n] : 0.f;
    jb.dst[(size_t)kp * jb.Nn + n] = f16_pack(f0, f1);
}

// ---------------- fp16 GEMM, packed-B, cp.async 3-stage pipeline ----------------
// C = act(A @ B + bias); A fp16 [M][lda], Bp packed half2 k-pairs [ceil(K/2)][Nn].
struct GArgs {
    const __half* A; int lda; int K;
    const uint32_t* Bp;
    void* C; int ldc;
};

static constexpr int A_PAD_H   = 40;
static constexpr int A_BYTES   = 128 * A_PAD_H * 2;        // 10240
static constexpr int B_PADW    = 136;                      // u32 per B smem row
static constexpr int B_BYTES   = 16 * B_PADW * 4;          // 8704
static constexpr int STG_BYTES = A_BYTES + B_BYTES;        // 18944
static constexpr int STAGES    = 3;
static constexpr int GM_SMEM   = STAGES * STG_BYTES;       // 56832

__global__ __launch_bounds__(256, 2)
void gemm_h(GArgs za, GArgs zb, int ldb, const float* __restrict__ bias,
            int Nn, int doRelu, int outHalf)
{
    extern __shared__ char smc[];
    GArgs ga = (blockIdx.z == 0) ? za : zb;

    const int tid  = threadIdx.x;
    const int wid  = tid >> 5;
    const int lane = tid & 31;
    const int g    = lane >> 2;
    const int t    = lane & 3;
    const int m0   = blockIdx.y * 128;
    const int n0   = blockIdx.x * 128;
    const int K    = ga.K;
    const int KP   = (K + 1) / 2;
    const int nT   = (K + 31) / 32;
    const int wm   = wid & 3;
    const int wn   = wid >> 2;
    const bool b_vec = ((Nn & 3) == 0);

    const uint32_t smb = smem_u32(smc);

    float acc[2][8][4];
#pragma unroll
    for (int i = 0; i < 2; i++)
#pragma unroll
        for (int j = 0; j < 8; j++)
#pragma unroll
            for (int k = 0; k < 4; k++) acc[i][j][k] = 0.f;

    auto issue_load = [&](int tt, int buf) {
        if (tt < nT) {
            const int k0 = tt * 32;
            const int kp0 = tt * 16;
            uint32_t Ab = smb + (uint32_t)buf * STG_BYTES;
            uint32_t Bb_ = Ab + A_BYTES;
#pragma unroll
            for (int i = 0; i < 2; i++) {
                int idx = i * 256 + tid;
                int row = idx >> 2, c8 = idx & 3;
                int kb = k0 + c8 * 8;
                const __half* src = ga.A;
                int sz = 0;
                if (kb < K) { src = ga.A + (size_t)(m0 + row) * ga.lda + kb; sz = 16; }
                cp_async16(Ab + (uint32_t)(row * (A_PAD_H * 2) + c8 * 16), src, sz);
            }
            // B: 16 kp-rows x 128 n of u32 = 512 x 16B chunks, 2 per thread
            if (b_vec) {
#pragma unroll
                for (int i = 0; i < 2; i++) {
                    int idx = i * 256 + tid;
                    int kp = idx >> 5, n4 = idx & 31;
                    int kg = kp0 + kp;
                    int nb4 = n0 + n4 * 4;
                    const uint32_t* src = ga.Bp;
                    int sz = 0;
                    if (kg < KP && nb4 + 3 < Nn) { src = ga.Bp + (size_t)kg * ldb + nb4; sz = 16; }
                    cp_async16(Bb_ + (uint32_t)(kp * B_PADW + n4 * 4) * 4, src, sz);
                }
            } else {
#pragma unroll
                for (int i = 0; i < 2; i++) {
                    int idx = i * 256 + tid;
                    int kp = idx >> 5, n4 = idx & 31;
                    int kg = kp0 + kp;
#pragma unroll
                    for (int j = 0; j < 4; j++) {
                        int nn = n0 + n4 * 4 + j;
                        const uint32_t* src = ga.Bp;
                        int sz = 0;
                        if (kg < KP && nn < Nn) { src = ga.Bp + (size_t)kg * ldb + nn; sz = 4; }
                        cp_async4(Bb_ + (uint32_t)(kp * B_PADW + n4 * 4 + j) * 4, src, sz);
                    }
                }
            }
        }
        CP_COMMIT();
    };

    auto compute = [&](int buf) {
        const __half*   As = (const __half*)(smc + buf * STG_BYTES) + (wm * 32) * A_PAD_H;
        const uint32_t* Bs = (const uint32_t*)(smc + buf * STG_BYTES + A_BYTES) + wn * 64;
#pragma unroll
        for (int ks = 0; ks < 2; ks++) {
            uint32_t ah[2][4];
#pragma unroll
            for (int mb = 0; mb < 2; mb++) {
#pragma unroll
                for (int r = 0; r < 4; r++) {
                    int rowq = mb * 16 + g + (r & 1) * 8;
                    int kq   = ks * 16 + t * 2 + (r >> 1) * 8;
                    ah[mb][r] = *(const uint32_t*)(As + rowq * A_PAD_H + kq);
                }
            }
            uint32_t bh[8][2];
#pragma unroll
            for (int nb = 0; nb < 8; nb++) {
#pragma unroll
                for (int r = 0; r < 2; r++) {
                    int kp = ks * 8 + t + r * 4;
                    bh[nb][r] = Bs[kp * B_PADW + nb * 8 + g];
                }
            }
#pragma unroll
            for (int mb = 0; mb < 2; mb++) {
#pragma unroll
                for (int nb = 0; nb < 8; nb++) {
                    mma_f16(acc[mb][nb], ah[mb], bh[nb]);
                }
            }
        }
    };

#pragma unroll
    for (int s = 0; s < STAGES - 1; s++) issue_load(s, s);

    for (int tt = 0; tt < nT; tt++) {
        issue_load(tt + STAGES - 1, (tt + STAGES - 1) % STAGES);
        CP_WAIT(STAGES - 1);
        __syncthreads();
        compute(tt % STAGES);
        __syncthreads();
    }

    // ---- epilogue ----
#pragma unroll
    for (int mb = 0; mb < 2; mb++) {
#pragma unroll
        for (int nb = 0; nb < 8; nb++) {
            int n = n0 + wn * 64 + nb * 8 + t * 2;
            float bv0 = 0.f, bv1 = 0.f;
            if (bias) {
                if (n     < Nn) bv0 = bias[n];
                if (n + 1 < Nn) bv1 = bias[n + 1];
            }
#pragma unroll
            for (int h = 0; h < 2; h++) {
                int m = m0 + wm * 32 + mb * 16 + g + h * 8;
                float v0 = acc[mb][nb][h * 2 + 0] + bv0;
                float v1 = acc[mb][nb][h * 2 + 1] + bv1;
                if (doRelu) { v0 = fmaxf(v0, 0.f); v1 = fmaxf(v1, 0.f); }
                if (outHalf) {
                    if (n < Nn) {
                        __half2 hv = __floats2half2_rn(v0, v1);
                        *(uint32_t*)((__half*)ga.C + (size_t)m * ga.ldc + n) = *(uint32_t*)&hv;
                    }
                } else {
                    float* cp = (float*)ga.C + (size_t)m * ga.ldc + n;
                    if (n     < Nn) cp[0] = v0;
                    if (n + 1 < Nn) cp[1] = v1;
                }
            }
        }
    }
}

// ---------------- appearance aggregation (CSR gather, fp16 data) ----------------
__global__ __launch_bounds__(256)
void agg_app_kernel(const __half* __restrict__ P1h, const __half* __restrict__ P2h,
                    const __half* __restrict__ SPh, const float* __restrict__ b_e,
                    const int* __restrict__ esrc, const int* __restrict__ perm,
                    const int* __restrict__ row_start, __half* __restrict__ FA)
{
    const int n = blockIdx.x;
    const int tid = threadIdx.x;
    const int start = row_start[n];
    const int nb = row_start[n + 1] - start;

    uint2 p2 = *(const uint2*)(P2h + (size_t)n * 1024 + tid * 4);
    float2 b0 = __half22float2(*(__half2*)&p2.x);
    float2 b1 = __half22float2(*(__half2*)&p2.y);
    float4 be = ((const float4*)b_e)[tid];
    float bx = b0.x + be.x, by = b0.y + be.y, bz = b1.x + be.z, bw = b1.y + be.w;

    float4 acc = make_float4(0.f, 0.f, 0.f, 0.f);
#pragma unroll 2
    for (int i = 0; i < nb; i++) {
        int e = __ldg(&perm[start + i]);
        int s = __ldg(&esrc[e]);
        uint2 a = *(const uint2*)(P1h + (size_t)s * 1024 + tid * 4);
        uint2 c = *(const uint2*)(SPh + (size_t)e * 1024 + tid * 4);
        float2 a0 = __half22float2(*(__half2*)&a.x);
        float2 a1 = __half22float2(*(__half2*)&a.y);
        float2 c0 = __half22float2(*(__half2*)&c.x);
        float2 c1 = __half22float2(*(__half2*)&c.y);
        acc.x += fmaxf(a0.x + c0.x + bx, 0.f);
        acc.y += fmaxf(a0.y + c0.y + by, 0.f);
        acc.z += fmaxf(a1.x + c1.x + bz, 0.f);
        acc.w += fmaxf(a1.y + c1.y + bw, 0.f);
    }
    float inv = 1.0f / (float)max(nb, 1);
    __half2 o0 = __floats2half2_rn(acc.x * inv, acc.y * inv);
    __half2 o1 = __floats2half2_rn(acc.z * inv, acc.w * inv);
    uint2 o; o.x = *(uint32_t*)&o0; o.y = *(uint32_t*)&o1;
    *(uint2*)(FA + (size_t)n * 2048 + 1024 + tid * 4) = o;
}

// ---------------- language aggregation (CSR gather, fp16 data) ----------------
__global__ __launch_bounds__(96)
void agg_lang_kernel(const __half* __restrict__ Q1h, const __half* __restrict__ Q2h,
                     const float* __restrict__ b_el,
                     const int* __restrict__ esrc, const int* __restrict__ perm,
                     const int* __restrict__ row_start, __half* __restrict__ WA)
{
    const int n = blockIdx.x;
    const int c4 = threadIdx.x;
    if (c4 >= DL / 4) return;
    const int start = row_start[n];
    const int nb = row_start[n + 1] - start;

    uint2 q2 = *(const uint2*)(Q2h + (size_t)n * 304 + c4 * 4);
    float2 b0 = __half22float2(*(__half2*)&q2.x);
    float2 b1 = __half22float2(*(__half2*)&q2.y);
    float4 be = ((const float4*)b_el)[c4];
    float bx = b0.x + be.x, by = b0.y + be.y, bz = b1.x + be.z, bw = b1.y + be.w;

    float4 acc = make_float4(0.f, 0.f, 0.f, 0.f);
#pragma unroll 2
    for (int i = 0; i < nb; i++) {
        int e = __ldg(&perm[start + i]);
        int s = __ldg(&esrc[e]);
        uint2 a = *(const uint2*)(Q1h + (size_t)s * 304 + c4 * 4);
        float2 a0 = __half22float2(*(__half2*)&a.x);
        float2 a1 = __half22float2(*(__half2*)&a.y);
        acc.x += fmaxf(a0.x + bx, 0.f);
        acc.y += fmaxf(a0.y + by, 0.f);
        acc.z += fmaxf(a1.x + bz, 0.f);
        acc.w += fmaxf(a1.y + bw, 0.f);
    }
    float inv = 1.0f / (float)max(nb, 1);
    __half2 o0 = __floats2half2_rn(acc.x * inv, acc.y * inv);
    __half2 o1 = __floats2half2_rn(acc.z * inv, acc.w * inv);
    uint2 o; o.x = *(uint32_t*)&o0; o.y = *(uint32_t*)&o1;
    *(uint2*)(WA + (size_t)n * 608 + 300 + c4 * 4) = o;
}

// ---------------- readout ----------------
__global__ __launch_bounds__(128)
void readout_kernel(const float* __restrict__ Rd, const float* __restrict__ Rs,
                    const float* __restrict__ SPro,
                    const int* __restrict__ rsrc, const int* __restrict__ rdst,
                    float* __restrict__ pred)
{
    int e = blockIdx.x;
    int c = threadIdx.x;
    if (c >= NC) return;
    int s = rsrc[e];
    int d = rdst[e];
    pred[(size_t)e * NC + c] = Rd[(size_t)d * NC + c] + Rs[(size_t)s * NC + c]
                             + SPro[(size_t)e * NC + c];
}

// ---------------- host launcher ----------------
extern "C" void kernel_launch(void* const* d_in, const int* in_sizes, int n_in,
                              void* d_out, int out_size)
{
    const float* feat   = (const float*)d_in[0];
    const float* w2v    = (const float*)d_in[1];
    const float* s_f    = (const float*)d_in[2];
    const float* s_f_ro = (const float*)d_in[3];
    const float* W_e    = (const float*)d_in[4];
    const float* b_e    = (const float*)d_in[5];
    const float* W_el   = (const float*)d_in[6];
    const float* b_el   = (const float*)d_in[7];
    const float* W_nu   = (const float*)d_in[8];
    const float* b_nu   = (const float*)d_in[9];
    const float* W_nul  = (const float*)d_in[10];
    const float* b_nul  = (const float*)d_in[11];
    const float* W_p    = (const float*)d_in[12];
    const float* b_p    = (const float*)d_in[13];
    const int* esrc = (const int*)d_in[14];
    const int* edst = (const int*)d_in[15];
    const int* rsrc = (const int*)d_in[16];
    const int* rdst = (const int*)d_in[17];
    float* pred = (float*)d_out;

    float* sc = nullptr;
    cudaGetSymbolAddress((void**)&sc, g_scratch);
    __half* hs = nullptr;
    cudaGetSymbolAddress((void**)&hs, g_hscratch);
    uint32_t* ps = nullptr;
    cudaGetSymbolAddress((void**)&ps, g_pscratch);
    int* isc = nullptr;
    cudaGetSymbolAddress((void**)&isc, g_iscratch);

    float* RD   = sc + OFF_RD;
    float* RS   = sc + OFF_RS;
    float* SPRO = sc + OFF_SPRO;

    __half* FA    = hs + HOFF_FA;
    __half* WA    = hs + HOFF_WA;
    __half* NFA   = hs + HOFF_NFA;
    __half* P1h   = hs + HOFF_P1;
    __half* P2h   = hs + HOFF_P2;
    __half* Q1h   = hs + HOFF_Q1;
    __half* Q2h   = hs + HOFF_Q2;
    __half* SPh   = hs + HOFF_SP;
    __half* sfh   = hs + HOFF_SFH;
    __half* sfroh = hs + HOFF_SFRO;

    uint32_t* WE1p  = ps + POFF_WE1;
    uint32_t* WE2p  = ps + POFF_WE2;
    uint32_t* WSp   = ps + POFF_WS;
    uint32_t* WEL1p = ps + POFF_WEL1;
    uint32_t* WEL2p = ps + POFF_WEL2;
    uint32_t* WNUp  = ps + POFF_WNU;
    uint32_t* WNULp = ps + POFF_WNUL;
    uint32_t* WRDp  = ps + POFF_WRD;
    uint32_t* WRSp  = ps + POFF_WRS;
    uint32_t* WSPp  = ps + POFF_WSP;

    int* deg  = isc + IOFF_DEG;
    int* rows = isc + IOFF_RS_;
    int* cur  = isc + IOFF_CUR;
    int* perm = isc + IOFF_PERM;

    cudaFuncSetAttribute(gemm_h, cudaFuncAttributeMaxDynamicSharedMemorySize, GM_SMEM);

    // ---- conversions ----
    conv_node_kernel<<<N_NODES, 256>>>(feat, w2v, FA, WA, NFA);
    {
        size_t pairs = ((size_t)NE + NE_RO) * 8;
        conv_sf_kernel<<<(unsigned)((pairs + 255) / 256), 256>>>(s_f, s_f_ro, sfh, sfroh);
    }
    // ---- weight k-pair packing (single launch) ----
    {
        PJobs J;
        J.j[0]  = {W_e,                                   D,  1024, 1024, WE1p};
        J.j[1]  = {W_e + (size_t)D * D,                   D,  1024, 1024, WE2p};
        J.j[2]  = {W_e + (size_t)(2 * D) * D,             D,  16,   1024, WSp};
        J.j[3]  = {W_el,                                  DL, 300,  300,  WEL1p};
        J.j[4]  = {W_el + (size_t)DL * DL,                DL, 300,  300,  WEL2p};
        J.j[5]  = {W_nu,                                  D,  2048, 1024, WNUp};
        J.j[6]  = {W_nul,                                 DL, 600,  300,  WNULp};
        J.j[7]  = {W_p,                                   NC, 1324, 117,  WRDp};
        J.j[8]  = {W_p + (size_t)(D + DL + DS + DL) * NC, NC, 1024, 117,  WRSp};        // RS NF part: kp 0..511
        J.j[9]  = {W_p + (size_t)(D + DL + DS) * NC,      NC, 300,  117,  WRSp + 512 * 117}; // RS NFL part: kp 512..661
        J.j[10] = {W_p + (size_t)(D + DL) * NC,           NC, 16,   117,  WSPp};
        wpack_kernel<<<dim3(4, 1024, 11), 256>>>(J);
    }

    // ---- CSR build (by dst) ----
    zero_int_kernel<<<(N_NODES + 255) / 256, 256>>>(deg, N_NODES);
    hist_kernel<<<NE / 256, 256>>>(edst, deg);
    scan_kernel<<<1, 512>>>(deg, rows, cur);
    scatter_kernel<<<NE / 256, 256>>>(edst, cur, perm);

    dim3 blk(256);

    // ---- spatial pre-projections ----
    {   // SP[e] = s_f @ Ws  -> fp16 [NE,1024]
        GArgs a{sfh, 16, 16, WSp, SPh, 1024};
        gemm_h<<<dim3(8, NE / 128, 1), blk, GM_SMEM>>>(a, a, 1024, nullptr, D, 0, 1);
    }
    {   // SPro[e] = s_f_ro @ Wp3 + b_p -> fp32 [NE_RO,117]
        GArgs a{sfroh, 16, 16, WSPp, SPRO, NC};
        gemm_h<<<dim3(1, 256, 1), blk, GM_SMEM>>>(a, a, 117, b_p, NC, 0, 0);
    }

    // ---- node-level pre-projections ----
    {   // P1 = feat @ We_top ; P2 = feat @ We_mid
        GArgs a{FA, 2048, 1024, WE1p, P1h, 1024};
        GArgs b{FA, 2048, 1024, WE2p, P2h, 1024};
        gemm_h<<<dim3(8, 128, 2), blk, GM_SMEM>>>(a, b, 1024, nullptr, D, 0, 1);
    }
    {   // Q1 = w2v @ Wel_top ; Q2 = w2v @ Wel_bot
        GArgs a{WA, 608, 300, WEL1p, Q1h, 304};
        GArgs b{WA, 608, 300, WEL2p, Q2h, 304};
        gemm_h<<<dim3(3, 128, 2), blk, GM_SMEM>>>(a, b, 300, nullptr, DL, 0, 1);
    }

    // ---- aggregation (gather, no atomics) ----
    agg_app_kernel<<<N_NODES, 256>>>(P1h, P2h, SPh, b_e, esrc, perm, rows, FA);
    agg_lang_kernel<<<N_NODES, 96>>>(Q1h, Q2h, b_el, esrc, perm, rows, WA);

    // ---- node updates ----
    {   // NF = relu([feat|AGG] @ W_nu + b_nu) -> NFA cols 0..1023
        GArgs a{FA, 2048, 2048, WNUp, NFA, 1328};
        gemm_h<<<dim3(8, 128, 1), blk, GM_SMEM>>>(a, a, 1024, b_nu, D, 1, 1);
    }
    {   // NFL = relu([w2v|AGGL] @ W_nul + b_nul) -> NFA cols 1024..1323
        GArgs a{WA, 608, 600, WNULp, NFA + 1024, 1328};
        gemm_h<<<dim3(3, 128, 1), blk, GM_SMEM>>>(a, a, 300, b_nul, DL, 1, 1);
    }

    // ---- predictor pre-projections (RD & RS merged) ----
    {
        GArgs a{NFA, 1328, 1324, WRDp, RD, NC};
        GArgs b{NFA, 1328, 1324, WRSp, RS, NC};
        gemm_h<<<dim3(1, 128, 2), blk, GM_SMEM>>>(a, b, 117, nullptr, NC, 0, 0);
    }

    // ---- final edge readout ----
    readout_kernel<<<NE_RO, 128>>>(RD, RS, SPRO, rsrc, rdst, pred);
}

// round 16
// speedup vs baseline: 1.1009x; 1.1009x over previous
#include <cuda_runtime.h>
#include <cuda_fp16.h>
#include <cstdint>
#include <cstddef>

// ---------------- problem dimensions ----------------
static constexpr int N_NODES = 16384;
static constexpr int NE      = 131072;
static constexpr int NE_RO   = 32768;
static constexpr int D       = 1024;
static constexpr int DL      = 300;
static constexpr int DS      = 16;
static constexpr int NC      = 117;

// ---------------- fp32 scratch (readout precursors) ----------------
static constexpr size_t SZ_NC   = (size_t)N_NODES * NC;
static constexpr size_t SZ_SPRO = (size_t)NE_RO * NC;
static constexpr size_t OFF_RD   = 0;
static constexpr size_t OFF_RS   = OFF_RD + SZ_NC;
static constexpr size_t OFF_SPRO = OFF_RS + SZ_NC;
static constexpr size_t TOTAL_F32 = OFF_SPRO + SZ_SPRO;
__device__ float g_scratch[TOTAL_F32];

// ---------------- fp16 scratch ----------------
static constexpr size_t HOFF_FA   = 0;                               // [N][2048] = [feat|AGG]
static constexpr size_t HSZ_FA    = (size_t)N_NODES * 2048;
static constexpr size_t HOFF_WA   = HOFF_FA + HSZ_FA;                // [N][608]  = [w2v|AGGL|pad]
static constexpr size_t HSZ_WA    = (size_t)N_NODES * 608;
static constexpr size_t HOFF_NFA  = HOFF_WA + HSZ_WA;                // [N][1328] = [NF|NFL|pad]
static constexpr size_t HSZ_NFA   = (size_t)N_NODES * 1328;
static constexpr size_t HOFF_P1   = HOFF_NFA + HSZ_NFA;
static constexpr size_t HSZ_P     = (size_t)N_NODES * 1024;
static constexpr size_t HOFF_P2   = HOFF_P1 + HSZ_P;
static constexpr size_t HOFF_Q1   = HOFF_P2 + HSZ_P;
static constexpr size_t HSZ_Q     = (size_t)N_NODES * 304;
static constexpr size_t HOFF_Q2   = HOFF_Q1 + HSZ_Q;
static constexpr size_t HOFF_SP   = HOFF_Q2 + HSZ_Q;
static constexpr size_t HSZ_SP    = (size_t)NE * 1024;
static constexpr size_t HOFF_SFH  = HOFF_SP + HSZ_SP;
static constexpr size_t HSZ_SFH   = (size_t)NE * 16;
static constexpr size_t HOFF_SFRO = HOFF_SFH + HSZ_SFH;
static constexpr size_t HSZ_SFRO  = (size_t)NE_RO * 16;
static constexpr size_t TOTAL_H   = HOFF_SFRO + HSZ_SFRO;
__device__ __half g_hscratch[TOTAL_H];

// int scratch
static constexpr size_t IOFF_DEG  = 0;
static constexpr size_t IOFF_RS_  = IOFF_DEG + N_NODES;
static constexpr size_t IOFF_CUR  = IOFF_RS_ + N_NODES + 1;
static constexpr size_t IOFF_PERM = IOFF_CUR + N_NODES;
__device__ int g_iscratch[IOFF_PERM + NE];

// ---------------- CSR build kernels ----------------
__global__ void hist_kernel(const int* __restrict__ edst, int* __restrict__ deg) {
    int e = blockIdx.x * blockDim.x + threadIdx.x;
    if (e < NE) atomicAdd(&deg[edst[e]], 1);
}
__global__ __launch_bounds__(512)
void scan_kernel(const int* __restrict__ deg, int* __restrict__ row_start,
                 int* __restrict__ cursor) {
    __shared__ int part[512];
    int tid = threadIdx.x;
    int base = tid * 32;
    int loc[32];
    int s = 0;
#pragma unroll
    for (int j = 0; j < 32; j++) { loc[j] = s; s += deg[base + j]; }
    part[tid] = s;
    __syncthreads();
    for (int off = 1; off < 512; off <<= 1) {
        int v = (tid >= off) ? part[tid - off] : 0;
        __syncthreads();
        part[tid] += v;
        __syncthreads();
    }
    int pre = (tid > 0) ? part[tid - 1] : 0;
#pragma unroll
    for (int j = 0; j < 32; j++) {
        int v = pre + loc[j];
        row_start[base + j] = v;
        cursor[base + j] = v;
    }
    if (tid == 511) row_start[N_NODES] = part[511];
}
__global__ void scatter_kernel(const int* __restrict__ edst, int* __restrict__ cursor,
                               int* __restrict__ perm) {
    int e = blockIdx.x * blockDim.x + threadIdx.x;
    if (e < NE) {
        int pos = atomicAdd(&cursor[edst[e]], 1);
        perm[pos] = e;
    }
}

// ---------------- fused conversion kernel ----------------
// blocks [0, N_NODES): node features -> FA / WA (+ pad NFA)
// blocks [N_NODES, N_NODES + SF_BLOCKS): s_f / s_f_ro fp32->fp16 pair conversion
static constexpr size_t SF_PAIRS  = ((size_t)NE + NE_RO) * 8;
static constexpr int    SF_BLOCKS = (int)((SF_PAIRS + 255) / 256);

__global__ __launch_bounds__(256)
void conv_all_kernel(const float* __restrict__ feat, const float* __restrict__ w2v,
                     const float* __restrict__ s_f, const float* __restrict__ s_f_ro,
                     __half* __restrict__ FA, __half* __restrict__ WA,
                     __half* __restrict__ NFA,
                     __half* __restrict__ sfh, __half* __restrict__ sfroh)
{
    int tid = threadIdx.x;
    if (blockIdx.x < N_NODES) {
        int n = blockIdx.x;
        float4 f = *(const float4*)(feat + (size_t)n * 1024 + tid * 4);
        __half2 h0 = __floats2half2_rn(f.x, f.y);
        __half2 h1 = __floats2half2_rn(f.z, f.w);
        uint2 u; u.x = *(uint32_t*)&h0; u.y = *(uint32_t*)&h1;
        *(uint2*)(FA + (size_t)n * 2048 + tid * 4) = u;
        if (tid < 75) {
            float4 w = *(const float4*)(w2v + (size_t)n * 300 + tid * 4);
            __half2 g0 = __floats2half2_rn(w.x, w.y);
            __half2 g1 = __floats2half2_rn(w.z, w.w);
            uint2 v; v.x = *(uint32_t*)&g0; v.y = *(uint32_t*)&g1;
            *(uint2*)(WA + (size_t)n * 608 + tid * 4) = v;
        } else if (tid == 75) {
            uint2 z = make_uint2(0, 0);
            *(uint2*)(WA + (size_t)n * 608 + 600) = z;
            *(uint2*)(WA + (size_t)n * 608 + 604) = z;
        } else if (tid == 76) {
            uint2 z = make_uint2(0, 0);
            *(uint2*)(NFA + (size_t)n * 1328 + 1324) = z;
        }
    } else {
        size_t i = (size_t)(blockIdx.x - N_NODES) * 256 + tid;   // pair index
        size_t n1 = (size_t)NE * 8;
        if (i >= SF_PAIRS) return;
        if (i < n1) {
            float2 f = *(const float2*)(s_f + i * 2);
            __half2 h = __floats2half2_rn(f.x, f.y);
            *(uint32_t*)(sfh + i * 2) = *(uint32_t*)&h;
        } else {
            size_t j = i - n1;
            float2 f = *(const float2*)(s_f_ro + j * 2);
            __half2 h = __floats2half2_rn(f.x, f.y);
            *(uint32_t*)(sfroh + j * 2) = *(uint32_t*)&h;
        }
    }
}

// ---------------- fp16 pack + mma + cp.async helpers ----------------
__device__ __forceinline__ uint32_t f16_pack(float f0, float f1) {
    __half2 h = __floats2half2_rn(f0, f1);
    return *(uint32_t*)&h;
}
__device__ __forceinline__ void mma_f16(float* c, const uint32_t* a, const uint32_t* b) {
    asm volatile("mma.sync.aligned.m16n8k16.row.col.f32.f16.f16.f32 "
        "{%0,%1,%2,%3}, {%4,%5,%6,%7}, {%8,%9}, {%0,%1,%2,%3};"
        : "+f"(c[0]), "+f"(c[1]), "+f"(c[2]), "+f"(c[3])
        : "r"(a[0]), "r"(a[1]), "r"(a[2]), "r"(a[3]), "r"(b[0]), "r"(b[1]));
}
__device__ __forceinline__ uint32_t smem_u32(const void* p) {
    uint32_t a;
    asm("{ .reg .u64 t; cvta.to.shared.u64 t, %1; cvt.u32.u64 %0, t; }" : "=r"(a) : "l"(p));
    return a;
}
__device__ __forceinline__ void cp_async16(uint32_t dst, const void* src, int src_bytes) {
    asm volatile("cp.async.cg.shared.global [%0], [%1], 16, %2;"
                 :: "r"(dst), "l"(src), "r"(src_bytes) : "memory");
}
__device__ __forceinline__ void cp_async4(uint32_t dst, const void* src, int src_bytes) {
    asm volatile("cp.async.ca.shared.global [%0], [%1], 4, %2;"
                 :: "r"(dst), "l"(src), "r"(src_bytes) : "memory");
}
#define CP_COMMIT() asm volatile("cp.async.commit_group;" ::: "memory")
#define CP_WAIT(N)  asm volatile("cp.async.wait_group %0;" :: "n"(N) : "memory")

// ---------------- fp16-A GEMM, cp.async 3-stage pipeline (R14 body) ----------------
struct GArgs {
    const __half* A; int lda; int K;
    const float* B1; const float* B2; int KB1;
    void* C; int ldc;
};

static constexpr int A_PAD_H   = 40;
static constexpr int A_BYTES   = 128 * A_PAD_H * 2;        // 10240
static constexpr int B_PAD     = 132;
static constexpr int B_BYTES   = 32 * B_PAD * 4;           // 16896
static constexpr int STG_BYTES = A_BYTES + B_BYTES;        // 27136
static constexpr int STAGES    = 3;
static constexpr int GM_SMEM   = STAGES * STG_BYTES;       // 81408

__global__ __launch_bounds__(256, 2)
void gemm_h(GArgs za, GArgs zb, int ldb, const float* __restrict__ bias,
            int Nn, int doRelu, int outHalf)
{
    extern __shared__ char smc[];
    GArgs ga = (blockIdx.z == 0) ? za : zb;

    const int tid  = threadIdx.x;
    const int wid  = tid >> 5;
    const int lane = tid & 31;
    const int g    = lane >> 2;
    const int t    = lane & 3;
    const int m0   = blockIdx.y * 128;
    const int n0   = blockIdx.x * 128;
    const int K    = ga.K;
    const int nT   = (K + 31) / 32;
    const int wm   = wid & 3;
    const int wn   = wid >> 2;
    const bool b_vec = ((ldb & 3) == 0);

    const uint32_t smb = smem_u32(smc);

    float acc[2][8][4];
#pragma unroll
    for (int i = 0; i < 2; i++)
#pragma unroll
        for (int j = 0; j < 8; j++)
#pragma unroll
            for (int k = 0; k < 4; k++) acc[i][j][k] = 0.f;

    auto issue_load = [&](int tt, int buf) {
        if (tt < nT) {
            const int k0 = tt * 32;
            uint32_t Ab = smb + (uint32_t)buf * STG_BYTES;
            uint32_t Bb_ = Ab + A_BYTES;
#pragma unroll
            for (int i = 0; i < 2; i++) {
                int idx = i * 256 + tid;
                int row = idx >> 2, c8 = idx & 3;
                int kb = k0 + c8 * 8;
                const __half* src = ga.A;
                int sz = 0;
                if (kb < K) { src = ga.A + (size_t)(m0 + row) * ga.lda + kb; sz = 16; }
                cp_async16(Ab + (uint32_t)(row * (A_PAD_H * 2) + c8 * 16), src, sz);
            }
            if (b_vec) {
#pragma unroll
                for (int i = 0; i < 4; i++) {
                    int idx = i * 256 + tid;
                    int k = idx >> 5, n4 = idx & 31;
                    int kg = k0 + k;
                    int nb4 = n0 + n4 * 4;
                    const float* src = ga.B1;
                    int sz = 0;
                    if (kg < K && nb4 + 3 < Nn) {
                        src = (kg < ga.KB1) ? (ga.B1 + (size_t)kg * ldb + nb4)
                                            : (ga.B2 + (size_t)(kg - ga.KB1) * ldb + nb4);
                        sz = 16;
                    }
                    cp_async16(Bb_ + (uint32_t)(k * B_PAD + n4 * 4) * 4, src, sz);
                }
            } else {
#pragma unroll
                for (int i = 0; i < 4; i++) {
                    int idx = i * 256 + tid;
                    int k = idx >> 5, n4 = idx & 31;
                    int kg = k0 + k;
#pragma unroll
                    for (int j = 0; j < 4; j++) {
                        int nn = n0 + n4 * 4 + j;
                        const float* src = ga.B1;
                        int sz = 0;
                        if (kg < K && nn < Nn) {
                            src = (kg < ga.KB1) ? (ga.B1 + (size_t)kg * ldb + nn)
                                                : (ga.B2 + (size_t)(kg - ga.KB1) * ldb + nn);
                            sz = 4;
                        }
                        cp_async4(Bb_ + (uint32_t)(k * B_PAD + n4 * 4 + j) * 4, src, sz);
                    }
                }
            }
        }
        CP_COMMIT();
    };

    auto compute = [&](int buf) {
        const __half* As = (const __half*)(smc + buf * STG_BYTES) + (wm * 32) * A_PAD_H;
        const float*  Bs = (const float*)(smc + buf * STG_BYTES + A_BYTES) + wn * 64;
#pragma unroll
        for (int ks = 0; ks < 2; ks++) {
            uint32_t ah[2][4];
#pragma unroll
            for (int mb = 0; mb < 2; mb++) {
#pragma unroll
                for (int r = 0; r < 4; r++) {
                    int rowq = mb * 16 + g + (r & 1) * 8;
                    int kq   = ks * 16 + t * 2 + (r >> 1) * 8;
                    ah[mb][r] = *(const uint32_t*)(As + rowq * A_PAD_H + kq);
                }
            }
            uint32_t bh[8][2];
#pragma unroll
            for (int nb = 0; nb < 8; nb++) {
#pragma unroll
                for (int r = 0; r < 2; r++) {
                    int kq = ks * 16 + t * 2 + r * 8;
                    float f0 = Bs[kq * B_PAD + nb * 8 + g];
                    float f1 = Bs[(kq + 1) * B_PAD + nb * 8 + g];
                    bh[nb][r] = f16_pack(f0, f1);
                }
            }
#pragma unroll
            for (int mb = 0; mb < 2; mb++) {
#pragma unroll
                for (int nb = 0; nb < 8; nb++) {
                    mma_f16(acc[mb][nb], ah[mb], bh[nb]);
                }
            }
        }
    };

#pragma unroll
    for (int s = 0; s < STAGES - 1; s++) issue_load(s, s);

    for (int tt = 0; tt < nT; tt++) {
        issue_load(tt + STAGES - 1, (tt + STAGES - 1) % STAGES);
        CP_WAIT(STAGES - 1);
        __syncthreads();
        compute(tt % STAGES);
        __syncthreads();
    }

    // ---- epilogue ----
#pragma unroll
    for (int mb = 0; mb < 2; mb++) {
#pragma unroll
        for (int nb = 0; nb < 8; nb++) {
            int n = n0 + wn * 64 + nb * 8 + t * 2;
            float bv0 = 0.f, bv1 = 0.f;
            if (bias) {
                if (n     < Nn) bv0 = bias[n];
                if (n + 1 < Nn) bv1 = bias[n + 1];
            }
#pragma unroll
            for (int h = 0; h < 2; h++) {
                int m = m0 + wm * 32 + mb * 16 + g + h * 8;
                float v0 = acc[mb][nb][h * 2 + 0] + bv0;
                float v1 = acc[mb][nb][h * 2 + 1] + bv1;
                if (doRelu) { v0 = fmaxf(v0, 0.f); v1 = fmaxf(v1, 0.f); }
                if (outHalf) {
                    if (n < Nn) {
                        __half2 hv = __floats2half2_rn(v0, v1);
                        *(uint32_t*)((__half*)ga.C + (size_t)m * ga.ldc + n) = *(uint32_t*)&hv;
                    }
                } else {
                    float* cp = (float*)ga.C + (size_t)m * ga.ldc + n;
                    if (n     < Nn) cp[0] = v0;
                    if (n + 1 < Nn) cp[1] = v1;
                }
            }
        }
    }
}

// ---------------- appearance aggregation (CSR gather, fp16 data) ----------------
__global__ __launch_bounds__(256)
void agg_app_kernel(const __half* __restrict__ P1h, const __half* __restrict__ P2h,
                    const __half* __restrict__ SPh, const float* __restrict__ b_e,
                    const int* __restrict__ esrc, const int* __restrict__ perm,
                    const int* __restrict__ row_start, __half* __restrict__ FA)
{
    const int n = blockIdx.x;
    const int tid = threadIdx.x;
    const int start = row_start[n];
    const int nb = row_start[n + 1] - start;

    uint2 p2 = *(const uint2*)(P2h + (size_t)n * 1024 + tid * 4);
    float2 b0 = __half22float2(*(__half2*)&p2.x);
    float2 b1 = __half22float2(*(__half2*)&p2.y);
    float4 be = ((const float4*)b_e)[tid];
    float bx = b0.x + be.x, by = b0.y + be.y, bz = b1.x + be.z, bw = b1.y + be.w;

    float4 acc = make_float4(0.f, 0.f, 0.f, 0.f);
#pragma unroll 2
    for (int i = 0; i < nb; i++) {
        int e = __ldg(&perm[start + i]);
        int s = __ldg(&esrc[e]);
        uint2 a = *(const uint2*)(P1h + (size_t)s * 1024 + tid * 4);
        uint2 c = *(const uint2*)(SPh + (size_t)e * 1024 + tid * 4);
        float2 a0 = __half22float2(*(__half2*)&a.x);
        float2 a1 = __half22float2(*(__half2*)&a.y);
        float2 c0 = __half22float2(*(__half2*)&c.x);
        float2 c1 = __half22float2(*(__half2*)&c.y);
        acc.x += fmaxf(a0.x + c0.x + bx, 0.f);
        acc.y += fmaxf(a0.y + c0.y + by, 0.f);
        acc.z += fmaxf(a1.x + c1.x + bz, 0.f);
        acc.w += fmaxf(a1.y + c1.y + bw, 0.f);
    }
    float inv = 1.0f / (float)max(nb, 1);
    __half2 o0 = __floats2half2_rn(acc.x * inv, acc.y * inv);
    __half2 o1 = __floats2half2_rn(acc.z * inv, acc.w * inv);
    uint2 o; o.x = *(uint32_t*)&o0; o.y = *(uint32_t*)&o1;
    *(uint2*)(FA + (size_t)n * 2048 + 1024 + tid * 4) = o;
}

// ---------------- language aggregation (CSR gather, fp16 data) ----------------
__global__ __launch_bounds__(96)
void agg_lang_kernel(const __half* __restrict__ Q1h, const __half* __restrict__ Q2h,
                     const float* __restrict__ b_el,
                     const int* __restrict__ esrc, const int* __restrict__ perm,
                     const int* __restrict__ row_start, __half* __restrict__ WA)
{
    const int n = blockIdx.x;
    const int c4 = threadIdx.x;
    if (c4 >= DL / 4) return;
    const int start = row_start[n];
    const int nb = row_start[n + 1] - start;

    uint2 q2 = *(const uint2*)(Q2h + (size_t)n * 304 + c4 * 4);
    float2 b0 = __half22float2(*(__half2*)&q2.x);
    float2 b1 = __half22float2(*(__half2*)&q2.y);
    float4 be = ((const float4*)b_el)[c4];
    float bx = b0.x + be.x, by = b0.y + be.y, bz = b1.x + be.z, bw = b1.y + be.w;

    float4 acc = make_float4(0.f, 0.f, 0.f, 0.f);
#pragma unroll 2
    for (int i = 0; i < nb; i++) {
        int e = __ldg(&perm[start + i]);
        int s = __ldg(&esrc[e]);
        uint2 a = *(const uint2*)(Q1h + (size_t)s * 304 + c4 * 4);
        float2 a0 = __half22float2(*(__half2*)&a.x);
        float2 a1 = __half22float2(*(__half2*)&a.y);
        acc.x += fmaxf(a0.x + bx, 0.f);
        acc.y += fmaxf(a0.y + by, 0.f);
        acc.z += fmaxf(a1.x + bz, 0.f);
        acc.w += fmaxf(a1.y + bw, 0.f);
    }
    float inv = 1.0f / (float)max(nb, 1);
    __half2 o0 = __floats2half2_rn(acc.x * inv, acc.y * inv);
    __half2 o1 = __floats2half2_rn(acc.z * inv, acc.w * inv);
    uint2 o; o.x = *(uint32_t*)&o0; o.y = *(uint32_t*)&o1;
    *(uint2*)(WA + (size_t)n * 608 + 300 + c4 * 4) = o;
}

// ---------------- readout: 2 edges per block ----------------
__global__ __launch_bounds__(256)
void readout_kernel(const float* __restrict__ Rd, const float* __restrict__ Rs,
                    const float* __restrict__ SPro,
                    const int* __restrict__ rsrc, const int* __restrict__ rdst,
                    float* __restrict__ pred)
{
    int e = blockIdx.x * 2 + (threadIdx.x >> 7);
    int c = threadIdx.x & 127;
    if (c >= NC || e >= NE_RO) return;
    int s = rsrc[e];
    int d = rdst[e];
    pred[(size_t)e * NC + c] = Rd[(size_t)d * NC + c] + Rs[(size_t)s * NC + c]
                             + SPro[(size_t)e * NC + c];
}

// ---------------- host launcher ----------------
extern "C" void kernel_launch(void* const* d_in, const int* in_sizes, int n_in,
                              void* d_out, int out_size)
{
    const float* feat   = (const float*)d_in[0];
    const float* w2v    = (const float*)d_in[1];
    const float* s_f    = (const float*)d_in[2];
    const float* s_f_ro = (const float*)d_in[3];
    const float* W_e    = (const float*)d_in[4];
    const float* b_e    = (const float*)d_in[5];
    const float* W_el   = (const float*)d_in[6];
    const float* b_el   = (const float*)d_in[7];
    const float* W_nu   = (const float*)d_in[8];
    const float* b_nu   = (const float*)d_in[9];
    const float* W_nul  = (const float*)d_in[10];
    const float* b_nul  = (const float*)d_in[11];
    const float* W_p    = (const float*)d_in[12];
    const float* b_p    = (const float*)d_in[13];
    const int* esrc = (const int*)d_in[14];
    const int* edst = (const int*)d_in[15];
    const int* rsrc = (const int*)d_in[16];
    const int* rdst = (const int*)d_in[17];
    float* pred = (float*)d_out;

    float* sc = nullptr;
    cudaGetSymbolAddress((void**)&sc, g_scratch);
    __half* hs = nullptr;
    cudaGetSymbolAddress((void**)&hs, g_hscratch);
    int* isc = nullptr;
    cudaGetSymbolAddress((void**)&isc, g_iscratch);

    float* RD   = sc + OFF_RD;
    float* RS   = sc + OFF_RS;
    float* SPRO = sc + OFF_SPRO;

    __half* FA    = hs + HOFF_FA;
    __half* WA    = hs + HOFF_WA;
    __half* NFA   = hs + HOFF_NFA;
    __half* P1h   = hs + HOFF_P1;
    __half* P2h   = hs + HOFF_P2;
    __half* Q1h   = hs + HOFF_Q1;
    __half* Q2h   = hs + HOFF_Q2;
    __half* SPh   = hs + HOFF_SP;
    __half* sfh   = hs + HOFF_SFH;
    __half* sfroh = hs + HOFF_SFRO;

    int* deg  = isc + IOFF_DEG;
    int* rows = isc + IOFF_RS_;
    int* cur  = isc + IOFF_CUR;
    int* perm = isc + IOFF_PERM;

    cudaFuncSetAttribute(gemm_h, cudaFuncAttributeMaxDynamicSharedMemorySize, GM_SMEM);

    const float* Ws  = W_e + (size_t)(2 * D) * D;      // spatial rows of W_e, stride D
    const float* Wp3 = W_p + (size_t)(D + DL) * NC;    // spatial rows of W_p

    // ---- conversions (fused) ----
    conv_all_kernel<<<N_NODES + SF_BLOCKS, 256>>>(feat, w2v, s_f, s_f_ro,
                                                  FA, WA, NFA, sfh, sfroh);

    // ---- CSR build (by dst) ----
    cudaMemsetAsync(deg, 0, N_NODES * sizeof(int));
    hist_kernel<<<NE / 256, 256>>>(edst, deg);
    scan_kernel<<<1, 512>>>(deg, rows, cur);
    scatter_kernel<<<NE / 256, 256>>>(edst, cur, perm);

    dim3 blk(256);
    const int BIG = 1 << 28;

    // ---- spatial pre-projections ----
    {   // SP[e] = s_f @ Ws  -> fp16 [NE,1024]
        GArgs a{sfh, 16, 16, Ws, Ws, BIG, SPh, 1024};
        gemm_h<<<dim3(8, NE / 128, 1), blk, GM_SMEM>>>(a, a, D, nullptr, D, 0, 1);
    }
    {   // SPro[e] = s_f_ro @ Wp3 + b_p -> fp32 [NE_RO,117]
        GArgs a{sfroh, 16, 16, Wp3, Wp3, BIG, SPRO, NC};
        gemm_h<<<dim3(1, 256, 1), blk, GM_SMEM>>>(a, a, NC, b_p, NC, 0, 0);
    }

    // ---- node-level pre-projections ----
    {   // P1 = feat @ We_top ; P2 = feat @ We_mid
        GArgs a{FA, 2048, 1024, W_e, W_e, BIG, P1h, 1024};
        GArgs b{FA, 2048, 1024, W_e + (size_t)D * D, W_e, BIG, P2h, 1024};
        gemm_h<<<dim3(8, 128, 2), blk, GM_SMEM>>>(a, b, D, nullptr, D, 0, 1);
    }
    {   // Q1 = w2v @ Wel_top ; Q2 = w2v @ Wel_bot
        GArgs a{WA, 608, 300, W_el, W_el, BIG, Q1h, 304};
        GArgs b{WA, 608, 300, W_el + (size_t)DL * DL, W_el, BIG, Q2h, 304};
        gemm_h<<<dim3(3, 128, 2), blk, GM_SMEM>>>(a, b, DL, nullptr, DL, 0, 1);
    }

    // ---- aggregation (gather, no atomics) ----
    agg_app_kernel<<<N_NODES, 256>>>(P1h, P2h, SPh, b_e, esrc, perm, rows, FA);
    agg_lang_kernel<<<N_NODES, 96>>>(Q1h, Q2h, b_el, esrc, perm, rows, WA);

    // ---- node updates ----
    {   // NF = relu([feat|AGG] @ W_nu + b_nu) -> NFA cols 0..1023
        GArgs a{FA, 2048, 2048, W_nu, W_nu, BIG, NFA, 1328};
        gemm_h<<<dim3(8, 128, 1), blk, GM_SMEM>>>(a, a, D, b_nu, D, 1, 1);
    }
    {   // NFL = relu([w2v|AGGL] @ W_nul + b_nul) -> NFA cols 1024..1323
        GArgs a{WA, 608, 600, W_nul, W_nul, BIG, NFA + 1024, 1328};
        gemm_h<<<dim3(3, 128, 1), blk, GM_SMEM>>>(a, a, DL, b_nul, DL, 1, 1);
    }

    // ---- predictor pre-projections (RD & RS merged; RS via two-segment B) ----
    {
        GArgs a{NFA, 1328, 1324, W_p, W_p, BIG, RD, NC};
        GArgs b{NFA, 1328, 1324,
                W_p + (size_t)(D + DL + DS + DL) * NC,   // NF part: rows 1640..2663
                W_p + (size_t)(D + DL + DS) * NC,        // NFL part: rows 1340..1639
                1024, RS, NC};
        gemm_h<<<dim3(1, 128, 2), blk, GM_SMEM>>>(a, b, NC, nullptr, NC, 0, 0);
    }

    // ---- final edge readout ----
    readout_kernel<<<NE_RO / 2, 256>>>(RD, RS, SPRO, rsrc, rdst, pred);
}

// round 17
// speedup vs baseline: 1.1731x; 1.0656x over previous
#include <cuda_runtime.h>
#include <cuda_fp16.h>
#include <cstdint>
#include <cstddef>

// ---------------- problem dimensions ----------------
static constexpr int N_NODES = 16384;
static constexpr int NE      = 131072;
static constexpr int NE_RO   = 32768;
static constexpr int D       = 1024;
static constexpr int DL      = 300;
static constexpr int DS      = 16;
static constexpr int NC      = 117;

// ---------------- fp32 scratch (readout precursors) ----------------
static constexpr size_t SZ_NC   = (size_t)N_NODES * NC;
static constexpr size_t SZ_SPRO = (size_t)NE_RO * NC;
static constexpr size_t OFF_RD   = 0;
static constexpr size_t OFF_RS   = OFF_RD + SZ_NC;
static constexpr size_t OFF_SPRO = OFF_RS + SZ_NC;
static constexpr size_t TOTAL_F32 = OFF_SPRO + SZ_SPRO;
__device__ float g_scratch[TOTAL_F32];

// ---------------- fp16 scratch ----------------
static constexpr size_t HOFF_FA   = 0;                               // [N][2048] = [feat|AGG]
static constexpr size_t HSZ_FA    = (size_t)N_NODES * 2048;
static constexpr size_t HOFF_WA   = HOFF_FA + HSZ_FA;                // [N][608]  = [w2v|AGGL|pad]
static constexpr size_t HSZ_WA    = (size_t)N_NODES * 608;
static constexpr size_t HOFF_NFA  = HOFF_WA + HSZ_WA;                // [N][1328] = [NF|NFL|pad]
static constexpr size_t HSZ_NFA   = (size_t)N_NODES * 1328;
static constexpr size_t HOFF_P1   = HOFF_NFA + HSZ_NFA;
static constexpr size_t HSZ_P     = (size_t)N_NODES * 1024;
static constexpr size_t HOFF_P2   = HOFF_P1 + HSZ_P;
static constexpr size_t HOFF_Q1   = HOFF_P2 + HSZ_P;
static constexpr size_t HSZ_Q     = (size_t)N_NODES * 304;
static constexpr size_t HOFF_Q2   = HOFF_Q1 + HSZ_Q;
static constexpr size_t HOFF_SP   = HOFF_Q2 + HSZ_Q;
static constexpr size_t HSZ_SP    = (size_t)NE * 1024;
static constexpr size_t HOFF_SFH  = HOFF_SP + HSZ_SP;
static constexpr size_t HSZ_SFH   = (size_t)NE * 16;
static constexpr size_t HOFF_SFRO = HOFF_SFH + HSZ_SFH;
static constexpr size_t HSZ_SFRO  = (size_t)NE_RO * 16;
static constexpr size_t TOTAL_H   = HOFF_SFRO + HSZ_SFRO;
__device__ __half g_hscratch[TOTAL_H];

// int scratch
static constexpr size_t IOFF_DEG  = 0;
static constexpr size_t IOFF_RS_  = IOFF_DEG + N_NODES;
static constexpr size_t IOFF_CUR  = IOFF_RS_ + N_NODES + 1;
static constexpr size_t IOFF_PERM = IOFF_CUR + N_NODES;
__device__ int g_iscratch[IOFF_PERM + NE];

// ---------------- CSR build kernels ----------------
__global__ void hist_kernel(const int* __restrict__ edst, int* __restrict__ deg) {
    int e = blockIdx.x * blockDim.x + threadIdx.x;
    if (e < NE) atomicAdd(&deg[edst[e]], 1);
}
__global__ __launch_bounds__(512)
void scan_kernel(const int* __restrict__ deg, int* __restrict__ row_start,
                 int* __restrict__ cursor) {
    __shared__ int part[512];
    int tid = threadIdx.x;
    int base = tid * 32;
    int loc[32];
    int s = 0;
#pragma unroll
    for (int j = 0; j < 32; j++) { loc[j] = s; s += deg[base + j]; }
    part[tid] = s;
    __syncthreads();
    for (int off = 1; off < 512; off <<= 1) {
        int v = (tid >= off) ? part[tid - off] : 0;
        __syncthreads();
        part[tid] += v;
        __syncthreads();
    }
    int pre = (tid > 0) ? part[tid - 1] : 0;
#pragma unroll
    for (int j = 0; j < 32; j++) {
        int v = pre + loc[j];
        row_start[base + j] = v;
        cursor[base + j] = v;
    }
    if (tid == 511) row_start[N_NODES] = part[511];
}
__global__ void scatter_kernel(const int* __restrict__ edst, int* __restrict__ cursor,
                               int* __restrict__ perm) {
    int e = blockIdx.x * blockDim.x + threadIdx.x;
    if (e < NE) {
        int pos = atomicAdd(&cursor[edst[e]], 1);
        perm[pos] = e;
    }
}

// ---------------- fused conversion kernel ----------------
static constexpr size_t SF_PAIRS  = ((size_t)NE + NE_RO) * 8;
static constexpr int    SF_BLOCKS = (int)((SF_PAIRS + 255) / 256);

__global__ __launch_bounds__(256)
void conv_all_kernel(const float* __restrict__ feat, const float* __restrict__ w2v,
                     const float* __restrict__ s_f, const float* __restrict__ s_f_ro,
                     __half* __restrict__ FA, __half* __restrict__ WA,
                     __half* __restrict__ NFA,
                     __half* __restrict__ sfh, __half* __restrict__ sfroh)
{
    int tid = threadIdx.x;
    if (blockIdx.x < N_NODES) {
        int n = blockIdx.x;
        float4 f = *(const float4*)(feat + (size_t)n * 1024 + tid * 4);
        __half2 h0 = __floats2half2_rn(f.x, f.y);
        __half2 h1 = __floats2half2_rn(f.z, f.w);
        uint2 u; u.x = *(uint32_t*)&h0; u.y = *(uint32_t*)&h1;
        *(uint2*)(FA + (size_t)n * 2048 + tid * 4) = u;
        if (tid < 75) {
            float4 w = *(const float4*)(w2v + (size_t)n * 300 + tid * 4);
            __half2 g0 = __floats2half2_rn(w.x, w.y);
            __half2 g1 = __floats2half2_rn(w.z, w.w);
            uint2 v; v.x = *(uint32_t*)&g0; v.y = *(uint32_t*)&g1;
            *(uint2*)(WA + (size_t)n * 608 + tid * 4) = v;
        } else if (tid == 75) {
            uint2 z = make_uint2(0, 0);
            *(uint2*)(WA + (size_t)n * 608 + 600) = z;
            *(uint2*)(WA + (size_t)n * 608 + 604) = z;
        } else if (tid == 76) {
            uint2 z = make_uint2(0, 0);
            *(uint2*)(NFA + (size_t)n * 1328 + 1324) = z;
        }
    } else {
        size_t i = (size_t)(blockIdx.x - N_NODES) * 256 + tid;
        size_t n1 = (size_t)NE * 8;
        if (i >= SF_PAIRS) return;
        if (i < n1) {
            float2 f = *(const float2*)(s_f + i * 2);
            __half2 h = __floats2half2_rn(f.x, f.y);
            *(uint32_t*)(sfh + i * 2) = *(uint32_t*)&h;
        } else {
            size_t j = i - n1;
            float2 f = *(const float2*)(s_f_ro + j * 2);
            __half2 h = __floats2half2_rn(f.x, f.y);
            *(uint32_t*)(sfroh + j * 2) = *(uint32_t*)&h;
        }
    }
}

// ---------------- fp16 pack + mma + cp.async helpers ----------------
__device__ __forceinline__ uint32_t f16_pack(float f0, float f1) {
    __half2 h = __floats2half2_rn(f0, f1);
    return *(uint32_t*)&h;
}
__device__ __forceinline__ void mma_f16(float* c, const uint32_t* a, const uint32_t* b) {
    asm volatile("mma.sync.aligned.m16n8k16.row.col.f32.f16.f16.f32 "
        "{%0,%1,%2,%3}, {%4,%5,%6,%7}, {%8,%9}, {%0,%1,%2,%3};"
        : "+f"(c[0]), "+f"(c[1]), "+f"(c[2]), "+f"(c[3])
        : "r"(a[0]), "r"(a[1]), "r"(a[2]), "r"(a[3]), "r"(b[0]), "r"(b[1]));
}
__device__ __forceinline__ uint32_t smem_u32(const void* p) {
    uint32_t a;
    asm("{ .reg .u64 t; cvta.to.shared.u64 t, %1; cvt.u32.u64 %0, t; }" : "=r"(a) : "l"(p));
    return a;
}
__device__ __forceinline__ void cp_async16(uint32_t dst, const void* src, int src_bytes) {
    asm volatile("cp.async.cg.shared.global [%0], [%1], 16, %2;"
                 :: "r"(dst), "l"(src), "r"(src_bytes) : "memory");
}
__device__ __forceinline__ void cp_async4(uint32_t dst, const void* src, int src_bytes) {
    asm volatile("cp.async.ca.shared.global [%0], [%1], 4, %2;"
                 :: "r"(dst), "l"(src), "r"(src_bytes) : "memory");
}
#define CP_COMMIT() asm volatile("cp.async.commit_group;" ::: "memory")
#define CP_WAIT(N)  asm volatile("cp.async.wait_group %0;" :: "n"(N) : "memory")

// ---------------- fp16-A GEMM, cp.async 4-stage pipeline ----------------
struct GArgs {
    const __half* A; int lda; int K;
    const float* B1; const float* B2; int KB1;
    void* C; int ldc;
};

static constexpr int A_PAD_H   = 40;
static constexpr int A_BYTES   = 128 * A_PAD_H * 2;        // 10240
static constexpr int B_PAD     = 132;
static constexpr int B_BYTES   = 32 * B_PAD * 4;           // 16896
static constexpr int STG_BYTES = A_BYTES + B_BYTES;        // 27136
static constexpr int STAGES    = 4;
static constexpr int GM_SMEM   = STAGES * STG_BYTES;       // 108544

__global__ __launch_bounds__(256, 2)
void gemm_h(GArgs za, GArgs zb, int ldb, const float* __restrict__ bias,
            int Nn, int doRelu, int outHalf)
{
    extern __shared__ char smc[];
    GArgs ga = (blockIdx.z == 0) ? za : zb;

    const int tid  = threadIdx.x;
    const int wid  = tid >> 5;
    const int lane = tid & 31;
    const int g    = lane >> 2;
    const int t    = lane & 3;
    const int m0   = blockIdx.y * 128;
    const int n0   = blockIdx.x * 128;
    const int K    = ga.K;
    const int nT   = (K + 31) / 32;
    const int wm   = wid & 3;
    const int wn   = wid >> 2;
    const bool b_vec = ((ldb & 3) == 0);

    const uint32_t smb = smem_u32(smc);

    float acc[2][8][4];
#pragma unroll
    for (int i = 0; i < 2; i++)
#pragma unroll
        for (int j = 0; j < 8; j++)
#pragma unroll
            for (int k = 0; k < 4; k++) acc[i][j][k] = 0.f;

    auto issue_load = [&](int tt, int buf) {
        if (tt < nT) {
            const int k0 = tt * 32;
            uint32_t Ab = smb + (uint32_t)buf * STG_BYTES;
            uint32_t Bb_ = Ab + A_BYTES;
#pragma unroll
            for (int i = 0; i < 2; i++) {
                int idx = i * 256 + tid;
                int row = idx >> 2, c8 = idx & 3;
                int kb = k0 + c8 * 8;
                const __half* src = ga.A;
                int sz = 0;
                if (kb < K) { src = ga.A + (size_t)(m0 + row) * ga.lda + kb; sz = 16; }
                cp_async16(Ab + (uint32_t)(row * (A_PAD_H * 2) + c8 * 16), src, sz);
            }
            if (b_vec) {
#pragma unroll
                for (int i = 0; i < 4; i++) {
                    int idx = i * 256 + tid;
                    int k = idx >> 5, n4 = idx & 31;
                    int kg = k0 + k;
                    int nb4 = n0 + n4 * 4;
                    const float* src = ga.B1;
                    int sz = 0;
                    if (kg < K && nb4 + 3 < Nn) {
                        src = (kg < ga.KB1) ? (ga.B1 + (size_t)kg * ldb + nb4)
                                            : (ga.B2 + (size_t)(kg - ga.KB1) * ldb + nb4);
                        sz = 16;
                    }
                    cp_async16(Bb_ + (uint32_t)(k * B_PAD + n4 * 4) * 4, src, sz);
                }
            } else {
#pragma unroll
                for (int i = 0; i < 4; i++) {
                    int idx = i * 256 + tid;
                    int k = idx >> 5, n4 = idx & 31;
                    int kg = k0 + k;
#pragma unroll
                    for (int j = 0; j < 4; j++) {
                        int nn = n0 + n4 * 4 + j;
                        const float* src = ga.B1;
                        int sz = 0;
                        if (kg < K && nn < Nn) {
                            src = (kg < ga.KB1) ? (ga.B1 + (size_t)kg * ldb + nn)
                                                : (ga.B2 + (size_t)(kg - ga.KB1) * ldb + nn);
                            sz = 4;
                        }
                        cp_async4(Bb_ + (uint32_t)(k * B_PAD + n4 * 4 + j) * 4, src, sz);
                    }
                }
            }
        }
        CP_COMMIT();
    };

    auto compute = [&](int buf) {
        const __half* As = (const __half*)(smc + buf * STG_BYTES) + (wm * 32) * A_PAD_H;
        const float*  Bs = (const float*)(smc + buf * STG_BYTES + A_BYTES) + wn * 64;
#pragma unroll
        for (int ks = 0; ks < 2; ks++) {
            uint32_t ah[2][4];
#pragma unroll
            for (int mb = 0; mb < 2; mb++) {
#pragma unroll
                for (int r = 0; r < 4; r++) {
                    int rowq = mb * 16 + g + (r & 1) * 8;
                    int kq   = ks * 16 + t * 2 + (r >> 1) * 8;
                    ah[mb][r] = *(const uint32_t*)(As + rowq * A_PAD_H + kq);
                }
            }
            uint32_t bh[8][2];
#pragma unroll
            for (int nb = 0; nb < 8; nb++) {
#pragma unroll
                for (int r = 0; r < 2; r++) {
                    int kq = ks * 16 + t * 2 + r * 8;
                    float f0 = Bs[kq * B_PAD + nb * 8 + g];
                    float f1 = Bs[(kq + 1) * B_PAD + nb * 8 + g];
                    bh[nb][r] = f16_pack(f0, f1);
                }
            }
#pragma unroll
            for (int mb = 0; mb < 2; mb++) {
#pragma unroll
                for (int nb = 0; nb < 8; nb++) {
                    mma_f16(acc[mb][nb], ah[mb], bh[nb]);
                }
            }
        }
    };

#pragma unroll
    for (int s = 0; s < STAGES - 1; s++) issue_load(s, s);

    for (int tt = 0; tt < nT; tt++) {
        issue_load(tt + STAGES - 1, (tt + STAGES - 1) % STAGES);
        CP_WAIT(STAGES - 1);
        __syncthreads();
        compute(tt % STAGES);
        __syncthreads();
    }

    // ---- epilogue ----
#pragma unroll
    for (int mb = 0; mb < 2; mb++) {
#pragma unroll
        for (int nb = 0; nb < 8; nb++) {
            int n = n0 + wn * 64 + nb * 8 + t * 2;
            float bv0 = 0.f, bv1 = 0.f;
            if (bias) {
                if (n     < Nn) bv0 = bias[n];
                if (n + 1 < Nn) bv1 = bias[n + 1];
            }
#pragma unroll
            for (int h = 0; h < 2; h++) {
                int m = m0 + wm * 32 + mb * 16 + g + h * 8;
                float v0 = acc[mb][nb][h * 2 + 0] + bv0;
                float v1 = acc[mb][nb][h * 2 + 1] + bv1;
                if (doRelu) { v0 = fmaxf(v0, 0.f); v1 = fmaxf(v1, 0.f); }
                if (outHalf) {
                    if (n < Nn) {
                        __half2 hv = __floats2half2_rn(v0, v1);
                        *(uint32_t*)((__half*)ga.C + (size_t)m * ga.ldc + n) = *(uint32_t*)&hv;
                    }
                } else {
                    float* cp = (float*)ga.C + (size_t)m * ga.ldc + n;
                    if (n     < Nn) cp[0] = v0;
                    if (n + 1 < Nn) cp[1] = v1;
                }
            }
        }
    }
}

// ---------------- appearance aggregation (CSR gather, fp16 data) ----------------
__global__ __launch_bounds__(256)
void agg_app_kernel(const __half* __restrict__ P1h, const __half* __restrict__ P2h,
                    const __half* __restrict__ SPh, const float* __restrict__ b_e,
                    const int* __restrict__ esrc, const int* __restrict__ perm,
                    const int* __restrict__ row_start, __half* __restrict__ FA)
{
    const int n = blockIdx.x;
    const int tid = threadIdx.x;
    const int start = row_start[n];
    const int nb = row_start[n + 1] - start;

    uint2 p2 = *(const uint2*)(P2h + (size_t)n * 1024 + tid * 4);
    float2 b0 = __half22float2(*(__half2*)&p2.x);
    float2 b1 = __half22float2(*(__half2*)&p2.y);
    float4 be = ((const float4*)b_e)[tid];
    float bx = b0.x + be.x, by = b0.y + be.y, bz = b1.x + be.z, bw = b1.y + be.w;

    float4 acc = make_float4(0.f, 0.f, 0.f, 0.f);
#pragma unroll 2
    for (int i = 0; i < nb; i++) {
        int e = __ldg(&perm[start + i]);
        int s = __ldg(&esrc[e]);
        uint2 a = *(const uint2*)(P1h + (size_t)s * 1024 + tid * 4);
        uint2 c = *(const uint2*)(SPh + (size_t)e * 1024 + tid * 4);
        float2 a0 = __half22float2(*(__half2*)&a.x);
        float2 a1 = __half22float2(*(__half2*)&a.y);
        float2 c0 = __half22float2(*(__half2*)&c.x);
        float2 c1 = __half22float2(*(__half2*)&c.y);
        acc.x += fmaxf(a0.x + c0.x + bx, 0.f);
        acc.y += fmaxf(a0.y + c0.y + by, 0.f);
        acc.z += fmaxf(a1.x + c1.x + bz, 0.f);
        acc.w += fmaxf(a1.y + c1.y + bw, 0.f);
    }
    float inv = 1.0f / (float)max(nb, 1);
    __half2 o0 = __floats2half2_rn(acc.x * inv, acc.y * inv);
    __half2 o1 = __floats2half2_rn(acc.z * inv, acc.w * inv);
    uint2 o; o.x = *(uint32_t*)&o0; o.y = *(uint32_t*)&o1;
    *(uint2*)(FA + (size_t)n * 2048 + 1024 + tid * 4) = o;
}

// ---------------- language aggregation (CSR gather, fp16 data) ----------------
__global__ __launch_bounds__(96)
void agg_lang_kernel(const __half* __restrict__ Q1h, const __half* __restrict__ Q2h,
                     const float* __restrict__ b_el,
                     const int* __restrict__ esrc, const int* __restrict__ perm,
                     const int* __restrict__ row_start, __half* __restrict__ WA)
{
    const int n = blockIdx.x;
    const int c4 = threadIdx.x;
    if (c4 >= DL / 4) return;
    const int start = row_start[n];
    const int nb = row_start[n + 1] - start;

    uint2 q2 = *(const uint2*)(Q2h + (size_t)n * 304 + c4 * 4);
    float2 b0 = __half22float2(*(__half2*)&q2.x);
    float2 b1 = __half22float2(*(__half2*)&q2.y);
    float4 be = ((const float4*)b_el)[c4];
    float bx = b0.x + be.x, by = b0.y + be.y, bz = b1.x + be.z, bw = b1.y + be.w;

    float4 acc = make_float4(0.f, 0.f, 0.f, 0.f);
#pragma unroll 2
    for (int i = 0; i < nb; i++) {
        int e = __ldg(&perm[start + i]);
        int s = __ldg(&esrc[e]);
        uint2 a = *(const uint2*)(Q1h + (size_t)s * 304 + c4 * 4);
        float2 a0 = __half22float2(*(__half2*)&a.x);
        float2 a1 = __half22float2(*(__half2*)&a.y);
        acc.x += fmaxf(a0.x + bx, 0.f);
        acc.y += fmaxf(a0.y + by, 0.f);
        acc.z += fmaxf(a1.x + bz, 0.f);
        acc.w += fmaxf(a1.y + bw, 0.f);
    }
    float inv = 1.0f / (float)max(nb, 1);
    __half2 o0 = __floats2half2_rn(acc.x * inv, acc.y * inv);
    __half2 o1 = __floats2half2_rn(acc.z * inv, acc.w * inv);
    uint2 o; o.x = *(uint32_t*)&o0; o.y = *(uint32_t*)&o1;
    *(uint2*)(WA + (size_t)n * 608 + 300 + c4 * 4) = o;
}

// ---------------- readout: 2 edges per block ----------------
__global__ __launch_bounds__(256)
void readout_kernel(const float* __restrict__ Rd, const float* __restrict__ Rs,
                    const float* __restrict__ SPro,
                    const int* __restrict__ rsrc, const int* __restrict__ rdst,
                    float* __restrict__ pred)
{
    int e = blockIdx.x * 2 + (threadIdx.x >> 7);
    int c = threadIdx.x & 127;
    if (c >= NC || e >= NE_RO) return;
    int s = rsrc[e];
    int d = rdst[e];
    pred[(size_t)e * NC + c] = Rd[(size_t)d * NC + c] + Rs[(size_t)s * NC + c]
                             + SPro[(size_t)e * NC + c];
}

// ---------------- host launcher ----------------
extern "C" void kernel_launch(void* const* d_in, const int* in_sizes, int n_in,
                              void* d_out, int out_size)
{
    const float* feat   = (const float*)d_in[0];
    const float* w2v    = (const float*)d_in[1];
    const float* s_f    = (const float*)d_in[2];
    const float* s_f_ro = (const float*)d_in[3];
    const float* W_e    = (const float*)d_in[4];
    const float* b_e    = (const float*)d_in[5];
    const float* W_el   = (const float*)d_in[6];
    const float* b_el   = (const float*)d_in[7];
    const float* W_nu   = (const float*)d_in[8];
    const float* b_nu   = (const float*)d_in[9];
    const float* W_nul  = (const float*)d_in[10];
    const float* b_nul  = (const float*)d_in[11];
    const float* W_p    = (const float*)d_in[12];
    const float* b_p    = (const float*)d_in[13];
    const int* esrc = (const int*)d_in[14];
    const int* edst = (const int*)d_in[15];
    const int* rsrc = (const int*)d_in[16];
    const int* rdst = (const int*)d_in[17];
    float* pred = (float*)d_out;

    float* sc = nullptr;
    cudaGetSymbolAddress((void**)&sc, g_scratch);
    __half* hs = nullptr;
    cudaGetSymbolAddress((void**)&hs, g_hscratch);
    int* isc = nullptr;
    cudaGetSymbolAddress((void**)&isc, g_iscratch);

    float* RD   = sc + OFF_RD;
    float* RS   = sc + OFF_RS;
    float* SPRO = sc + OFF_SPRO;

    __half* FA    = hs + HOFF_FA;
    __half* WA    = hs + HOFF_WA;
    __half* NFA   = hs + HOFF_NFA;
    __half* P1h   = hs + HOFF_P1;
    __half* P2h   = hs + HOFF_P2;
    __half* Q1h   = hs + HOFF_Q1;
    __half* Q2h   = hs + HOFF_Q2;
    __half* SPh   = hs + HOFF_SP;
    __half* sfh   = hs + HOFF_SFH;
    __half* sfroh = hs + HOFF_SFRO;

    int* deg  = isc + IOFF_DEG;
    int* rows = isc + IOFF_RS_;
    int* cur  = isc + IOFF_CUR;
    int* perm = isc + IOFF_PERM;

    cudaFuncSetAttribute(gemm_h, cudaFuncAttributeMaxDynamicSharedMemorySize, GM_SMEM);

    const float* Ws  = W_e + (size_t)(2 * D) * D;      // spatial rows of W_e, stride D
    const float* Wp3 = W_p + (size_t)(D + DL) * NC;    // spatial rows of W_p

    // ---- conversions (fused) ----
    conv_all_kernel<<<N_NODES + SF_BLOCKS, 256>>>(feat, w2v, s_f, s_f_ro,
                                                  FA, WA, NFA, sfh, sfroh);

    // ---- CSR build (by dst) ----
    cudaMemsetAsync(deg, 0, N_NODES * sizeof(int));
    hist_kernel<<<NE / 256, 256>>>(edst, deg);
    scan_kernel<<<1, 512>>>(deg, rows, cur);
    scatter_kernel<<<NE / 256, 256>>>(edst, cur, perm);

    dim3 blk(256);
    const int BIG = 1 << 28;

    // ---- spatial pre-projections ----
    {   // SP[e] = s_f @ Ws  -> fp16 [NE,1024]
        GArgs a{sfh, 16, 16, Ws, Ws, BIG, SPh, 1024};
        gemm_h<<<dim3(8, NE / 128, 1), blk, GM_SMEM>>>(a, a, D, nullptr, D, 0, 1);
    }
    {   // SPro[e] = s_f_ro @ Wp3 + b_p -> fp32 [NE_RO,117]
        GArgs a{sfroh, 16, 16, Wp3, Wp3, BIG, SPRO, NC};
        gemm_h<<<dim3(1, 256, 1), blk, GM_SMEM>>>(a, a, NC, b_p, NC, 0, 0);
    }

    // ---- node-level pre-projections ----
    {   // P1 = feat @ We_top ; P2 = feat @ We_mid
        GArgs a{FA, 2048, 1024, W_e, W_e, BIG, P1h, 1024};
        GArgs b{FA, 2048, 1024, W_e + (size_t)D * D, W_e, BIG, P2h, 1024};
        gemm_h<<<dim3(8, 128, 2), blk, GM_SMEM>>>(a, b, D, nullptr, D, 0, 1);
    }
    {   // Q1 = w2v @ Wel_top ; Q2 = w2v @ Wel_bot
        GArgs a{WA, 608, 300, W_el, W_el, BIG, Q1h, 304};
        GArgs b{WA, 608, 300, W_el + (size_t)DL * DL, W_el, BIG, Q2h, 304};
        gemm_h<<<dim3(3, 128, 2), blk, GM_SMEM>>>(a, b, DL, nullptr, DL, 0, 1);
    }

    // ---- aggregation (gather, no atomics) ----
    agg_app_kernel<<<N_NODES, 256>>>(P1h, P2h, SPh, b_e, esrc, perm, rows, FA);
    agg_lang_kernel<<<N_NODES, 96>>>(Q1h, Q2h, b_el, esrc, perm, rows, WA);

    // ---- node updates ----
    {   // NF = relu([feat|AGG] @ W_nu + b_nu) -> NFA cols 0..1023
        GArgs a{FA, 2048, 2048, W_nu, W_nu, BIG, NFA, 1328};
        gemm_h<<<dim3(8, 128, 1), blk, GM_SMEM>>>(a, a, D, b_nu, D, 1, 1);
    }
    {   // NFL = relu([w2v|AGGL] @ W_nul + b_nul) -> NFA cols 1024..1323
        GArgs a{WA, 608, 600, W_nul, W_nul, BIG, NFA + 1024, 1328};
        gemm_h<<<dim3(3, 128, 1), blk, GM_SMEM>>>(a, a, DL, b_nul, DL, 1, 1);
    }

    // ---- predictor pre-projections (RD & RS merged; RS via two-segment B) ----
    {
        GArgs a{NFA, 1328, 1324, W_p, W_p, BIG, RD, NC};
        GArgs b{NFA, 1328, 1324,
                W_p + (size_t)(D + DL + DS + DL) * NC,   // NF part: rows 1640..2663
                W_p + (size_t)(D + DL + DS) * NC,        // NFL part: rows 1340..1639
                1024, RS, NC};
        gemm_h<<<dim3(1, 128, 2), blk, GM_SMEM>>>(a, b, NC, nullptr, NC, 0, 0);
    }

    // ---- final edge readout ----
    readout_kernel<<<NE_RO / 2, 256>>>(RD, RS, SPRO, rsrc, rdst, pred);
}